// round 1
// baseline (speedup 1.0000x reference)
#include <cuda_runtime.h>

// SimpleAttention: y = softmax((XWq+bq)(XWk+bk)^T / sqrt(H)) (XWv+bv) Wh + bh
// B=4, S=2048, H=1024, OUT=1024. All fp32.

#define B_   4
#define S_   2048
#define H_   1024
#define MTOT (B_ * S_)   // 8192

// Scratch (static device globals -- allocation-free per harness rules)
__device__ float g_Q[(size_t)MTOT * H_];
__device__ float g_K[(size_t)MTOT * H_];
__device__ float g_V[(size_t)MTOT * H_];
__device__ float g_S[(size_t)B_ * S_ * S_];
__device__ float g_C[(size_t)MTOT * H_];

// ---------------------------------------------------------------------------
// 128x128 tiled fp32 GEMM, K-step 8, 256 threads, 8x8 microtile per thread.
// C[m,n] = alpha * sum_k A[m,k] * B(k,n) + bias[n]
//   TRANSB=false: B row-major [K,N]
//   TRANSB=true : B row-major [N,K]  (C = alpha * A * B^T)
// Requires M%128==0, N%128==0, K%8==0 (true for all shapes here).
// blockIdx.z batches via strides sA/sB/sC.
// ---------------------------------------------------------------------------
template <bool TRANSB, bool HAS_BIAS>
__global__ __launch_bounds__(256, 2)
void gemm128(const float* __restrict__ A, const float* __restrict__ Bm,
             const float* __restrict__ bias, float* __restrict__ C,
             int M, int N, int K, float alpha,
             size_t sA, size_t sB, size_t sC)
{
    A  += (size_t)blockIdx.z * sA;
    Bm += (size_t)blockIdx.z * sB;
    C  += (size_t)blockIdx.z * sC;

    __shared__ float As[8][132];   // [k][m], pad 132 (16B-aligned rows, conflict-free)
    __shared__ float Bs[8][132];   // [k][n]

    const int tid = threadIdx.x;
    const int tx  = tid & 15;      // 0..15  -> N direction
    const int ty  = tid >> 4;      // 0..15  -> M direction
    const int rowBase = blockIdx.y * 128;
    const int colBase = blockIdx.x * 128;

    // global-load mapping
    const int arow = tid >> 1;           // 0..127
    const int acol = (tid & 1) * 4;      // 0 or 4
    const int bkr  = tid >> 5;           // 0..7   (NN)
    const int bcol = (tid & 31) * 4;     // 0..124 (NN)

    const float* Aptr = A + (size_t)(rowBase + arow) * K + acol;
    const float* Bptr = TRANSB
        ? Bm + (size_t)(colBase + arow) * K + acol
        : Bm + (size_t)bkr * N + colBase + bcol;

    float acc[8][8];
#pragma unroll
    for (int i = 0; i < 8; i++)
#pragma unroll
        for (int j = 0; j < 8; j++) acc[i][j] = 0.0f;

    const int ntiles = K >> 3;

    // prologue prefetch
    float4 ra = *reinterpret_cast<const float4*>(Aptr);
    float4 rb = TRANSB
        ? *reinterpret_cast<const float4*>(Bptr)
        : *reinterpret_cast<const float4*>(Bptr);

    for (int t = 0; t < ntiles; t++) {
        // stage registers -> smem
        As[acol + 0][arow] = ra.x;
        As[acol + 1][arow] = ra.y;
        As[acol + 2][arow] = ra.z;
        As[acol + 3][arow] = ra.w;
        if (TRANSB) {
            Bs[acol + 0][arow] = rb.x;
            Bs[acol + 1][arow] = rb.y;
            Bs[acol + 2][arow] = rb.z;
            Bs[acol + 3][arow] = rb.w;
        } else {
            *reinterpret_cast<float4*>(&Bs[bkr][bcol]) = rb;
        }
        __syncthreads();

        // prefetch next K-slab while computing this one
        if (t + 1 < ntiles) {
            ra = *reinterpret_cast<const float4*>(Aptr + (size_t)(t + 1) * 8);
            if (TRANSB)
                rb = *reinterpret_cast<const float4*>(Bptr + (size_t)(t + 1) * 8);
            else
                rb = *reinterpret_cast<const float4*>(Bptr + (size_t)(t + 1) * 8 * N);
        }

#pragma unroll
        for (int k = 0; k < 8; k++) {
            float4 a0 = *reinterpret_cast<const float4*>(&As[k][ty * 4]);
            float4 a1 = *reinterpret_cast<const float4*>(&As[k][64 + ty * 4]);
            float4 b0 = *reinterpret_cast<const float4*>(&Bs[k][tx * 4]);
            float4 b1 = *reinterpret_cast<const float4*>(&Bs[k][64 + tx * 4]);
            float af[8] = {a0.x, a0.y, a0.z, a0.w, a1.x, a1.y, a1.z, a1.w};
            float bf[8] = {b0.x, b0.y, b0.z, b0.w, b1.x, b1.y, b1.z, b1.w};
#pragma unroll
            for (int i = 0; i < 8; i++)
#pragma unroll
                for (int j = 0; j < 8; j++)
                    acc[i][j] += af[i] * bf[j];
        }
        __syncthreads();
    }

    // epilogue
    float4 bias0 = make_float4(0.f, 0.f, 0.f, 0.f);
    float4 bias1 = make_float4(0.f, 0.f, 0.f, 0.f);
    if (HAS_BIAS) {
        bias0 = *reinterpret_cast<const float4*>(&bias[colBase + tx * 4]);
        bias1 = *reinterpret_cast<const float4*>(&bias[colBase + 64 + tx * 4]);
    }
    const int c0 = colBase + tx * 4;
    const int c1 = colBase + 64 + tx * 4;
#pragma unroll
    for (int i = 0; i < 8; i++) {
        const int r = rowBase + ((i < 4) ? (ty * 4 + i) : (64 + ty * 4 + (i - 4)));
        float4 v0, v1;
        v0.x = acc[i][0] * alpha + bias0.x;
        v0.y = acc[i][1] * alpha + bias0.y;
        v0.z = acc[i][2] * alpha + bias0.z;
        v0.w = acc[i][3] * alpha + bias0.w;
        v1.x = acc[i][4] * alpha + bias1.x;
        v1.y = acc[i][5] * alpha + bias1.y;
        v1.z = acc[i][6] * alpha + bias1.z;
        v1.w = acc[i][7] * alpha + bias1.w;
        *reinterpret_cast<float4*>(&C[(size_t)r * N + c0]) = v0;
        *reinterpret_cast<float4*>(&C[(size_t)r * N + c1]) = v1;
    }
}

// ---------------------------------------------------------------------------
// Row softmax over S_=2048 columns. One 256-thread block per row.
// ---------------------------------------------------------------------------
__global__ void softmax_rows(float* __restrict__ Sm)
{
    const int row  = blockIdx.x;
    const int tid  = threadIdx.x;
    const int lane = tid & 31;
    const int warp = tid >> 5;

    float4* p = reinterpret_cast<float4*>(Sm + (size_t)row * S_);

    float4 v0 = p[tid];
    float4 v1 = p[tid + 256];

    __shared__ float redMax[8];
    __shared__ float redSum[8];

    float m = fmaxf(fmaxf(fmaxf(v0.x, v0.y), fmaxf(v0.z, v0.w)),
                    fmaxf(fmaxf(v1.x, v1.y), fmaxf(v1.z, v1.w)));
#pragma unroll
    for (int o = 16; o > 0; o >>= 1)
        m = fmaxf(m, __shfl_xor_sync(0xFFFFFFFFu, m, o));
    if (lane == 0) redMax[warp] = m;
    __syncthreads();
    float mAll = redMax[0];
#pragma unroll
    for (int w = 1; w < 8; w++) mAll = fmaxf(mAll, redMax[w]);

    v0.x = __expf(v0.x - mAll);
    v0.y = __expf(v0.y - mAll);
    v0.z = __expf(v0.z - mAll);
    v0.w = __expf(v0.w - mAll);
    v1.x = __expf(v1.x - mAll);
    v1.y = __expf(v1.y - mAll);
    v1.z = __expf(v1.z - mAll);
    v1.w = __expf(v1.w - mAll);

    float s = (v0.x + v0.y) + (v0.z + v0.w) + (v1.x + v1.y) + (v1.z + v1.w);
#pragma unroll
    for (int o = 16; o > 0; o >>= 1)
        s += __shfl_xor_sync(0xFFFFFFFFu, s, o);
    if (lane == 0) redSum[warp] = s;
    __syncthreads();
    float sAll = 0.f;
#pragma unroll
    for (int w = 0; w < 8; w++) sAll += redSum[w];

    const float inv = 1.0f / sAll;
    v0.x *= inv; v0.y *= inv; v0.z *= inv; v0.w *= inv;
    v1.x *= inv; v1.y *= inv; v1.z *= inv; v1.w *= inv;

    p[tid]       = v0;
    p[tid + 256] = v1;
}

// ---------------------------------------------------------------------------
extern "C" void kernel_launch(void* const* d_in, const int* in_sizes, int n_in,
                              void* d_out, int out_size)
{
    const float* X  = (const float*)d_in[0];
    const float* Wq = (const float*)d_in[1];
    const float* bq = (const float*)d_in[2];
    const float* Wk = (const float*)d_in[3];
    const float* bk = (const float*)d_in[4];
    const float* Wv = (const float*)d_in[5];
    const float* bv = (const float*)d_in[6];
    const float* Wh = (const float*)d_in[7];
    const float* bh = (const float*)d_in[8];
    float* out = (float*)d_out;

    float *Q, *K, *V, *Sc, *C;
    cudaGetSymbolAddress((void**)&Q,  g_Q);
    cudaGetSymbolAddress((void**)&K,  g_K);
    cudaGetSymbolAddress((void**)&V,  g_V);
    cudaGetSymbolAddress((void**)&Sc, g_S);
    cudaGetSymbolAddress((void**)&C,  g_C);

    const dim3 blk(256);
    const float scale = 0.03125f;  // 1/sqrt(1024)

    // 1-3) Q, K, V projections: [8192,1024] = X[8192,1024] @ W[1024,1024] + b
    {
        dim3 grid(H_ / 128, MTOT / 128, 1);
        gemm128<false, true><<<grid, blk>>>(X, Wq, bq, Q, MTOT, H_, H_, 1.0f, 0, 0, 0);
        gemm128<false, true><<<grid, blk>>>(X, Wk, bk, K, MTOT, H_, H_, 1.0f, 0, 0, 0);
        gemm128<false, true><<<grid, blk>>>(X, Wv, bv, V, MTOT, H_, H_, 1.0f, 0, 0, 0);
    }

    // 4) scores: per batch  S = scale * Q_b @ K_b^T   [2048,2048]
    {
        dim3 grid(S_ / 128, S_ / 128, B_);
        gemm128<true, false><<<grid, blk>>>(Q, K, nullptr, Sc, S_, S_, H_, scale,
                                            (size_t)S_ * H_, (size_t)S_ * H_,
                                            (size_t)S_ * S_);
    }

    // 5) softmax rows
    softmax_rows<<<B_ * S_, blk>>>(Sc);

    // 6) context: per batch  C = S_b @ V_b   [2048,1024], K-dim 2048
    {
        dim3 grid(H_ / 128, S_ / 128, B_);
        gemm128<false, false><<<grid, blk>>>(Sc, V, nullptr, C, S_, H_, S_, 1.0f,
                                             (size_t)S_ * S_, (size_t)S_ * H_,
                                             (size_t)S_ * H_);
    }

    // 7) output projection: [8192,1024] = C @ Wh + bh
    {
        dim3 grid(H_ / 128, MTOT / 128, 1);
        gemm128<false, true><<<grid, blk>>>(C, Wh, bh, out, MTOT, H_, H_, 1.0f, 0, 0, 0);
    }
}

// round 3
// speedup vs baseline: 1.8647x; 1.8647x over previous
#include <cuda_runtime.h>
#include <cuda_bf16.h>
#include <cstdint>

// SimpleAttention via mma.sync (HMMA bf16, base sm_100 ISA):
// y = softmax((XWq+bq)(XWk+bk)^T/32)(XWv+bv) Wh + bh
// B=4, S=2048, H=1024. fp32 in/out; GEMMs via bf16 hi/lo split, 3-term MMA.

#define B_   4
#define S_   2048
#define H_   1024
#define MTOT (B_ * S_)   // 8192

// ------------------------------- scratch -----------------------------------
__device__ __align__(256) __nv_bfloat16 g_Xhi[(size_t)MTOT * H_];
__device__ __align__(256) __nv_bfloat16 g_Xlo[(size_t)MTOT * H_];
__device__ __align__(256) __nv_bfloat16 g_Qhi[(size_t)MTOT * H_];
__device__ __align__(256) __nv_bfloat16 g_Qlo[(size_t)MTOT * H_];
__device__ __align__(256) __nv_bfloat16 g_Khi[(size_t)MTOT * H_];
__device__ __align__(256) __nv_bfloat16 g_Klo[(size_t)MTOT * H_];
__device__ __align__(256) float         g_Vf [(size_t)MTOT * H_];
__device__ __align__(256) __nv_bfloat16 g_VThi[(size_t)MTOT * H_];  // [b][1024][2048]
__device__ __align__(256) __nv_bfloat16 g_VTlo[(size_t)MTOT * H_];
__device__ __align__(256) float         g_Sf [(size_t)B_ * S_ * S_];
__device__ __align__(256) __nv_bfloat16 g_Phi[(size_t)B_ * S_ * S_];
__device__ __align__(256) __nv_bfloat16 g_Plo[(size_t)B_ * S_ * S_];
__device__ __align__(256) __nv_bfloat16 g_Chi[(size_t)MTOT * H_];
__device__ __align__(256) __nv_bfloat16 g_Clo[(size_t)MTOT * H_];
__device__ __align__(256) __nv_bfloat16 g_WqThi[(size_t)H_ * H_];
__device__ __align__(256) __nv_bfloat16 g_WqTlo[(size_t)H_ * H_];
__device__ __align__(256) __nv_bfloat16 g_WkThi[(size_t)H_ * H_];
__device__ __align__(256) __nv_bfloat16 g_WkTlo[(size_t)H_ * H_];
__device__ __align__(256) __nv_bfloat16 g_WvThi[(size_t)H_ * H_];
__device__ __align__(256) __nv_bfloat16 g_WvTlo[(size_t)H_ * H_];
__device__ __align__(256) __nv_bfloat16 g_WhThi[(size_t)H_ * H_];
__device__ __align__(256) __nv_bfloat16 g_WhTlo[(size_t)H_ * H_];

// --------------------------- PTX helpers -----------------------------------
__device__ __forceinline__ uint32_t smem_u32(const void* p) {
    uint32_t a;
    asm("{ .reg .u64 t; cvta.to.shared.u64 t, %1; cvt.u32.u64 %0, t; }" : "=r"(a) : "l"(p));
    return a;
}
__device__ __forceinline__ void cp16(uint32_t dst, const void* src) {
    asm volatile("cp.async.cg.shared.global [%0], [%1], 16;" :: "r"(dst), "l"(src));
}
#define CP_COMMIT() asm volatile("cp.async.commit_group;" ::: "memory")
#define CP_WAIT(n)  asm volatile("cp.async.wait_group %0;" :: "n"(n) : "memory")

__device__ __forceinline__ void ldm4(uint32_t* r, uint32_t addr) {
    asm volatile("ldmatrix.sync.aligned.m8n8.x4.shared.b16 {%0,%1,%2,%3}, [%4];"
                 : "=r"(r[0]), "=r"(r[1]), "=r"(r[2]), "=r"(r[3]) : "r"(addr));
}
__device__ __forceinline__ void mma16816(float* d, const uint32_t* a, const uint32_t* b) {
    asm volatile("mma.sync.aligned.m16n8k16.row.col.f32.bf16.bf16.f32 "
                 "{%0,%1,%2,%3}, {%4,%5,%6,%7}, {%8,%9}, {%0,%1,%2,%3};"
                 : "+f"(d[0]), "+f"(d[1]), "+f"(d[2]), "+f"(d[3])
                 : "r"(a[0]), "r"(a[1]), "r"(a[2]), "r"(a[3]), "r"(b[0]), "r"(b[1]));
}

// --------------------------- bf16 mma GEMM ---------------------------------
// C[M,N] = alpha * A[M,K] @ B[N,K]^T + bias[N], via hi/lo bf16 split (3 terms)
// EPI 0: fp32 out. EPI 1: split bf16 hi/lo out.
static constexpr int KC     = 32;           // K per chunk (bf16 elems)
static constexpr int ROWB   = 80;           // bytes per smem row (64 data + 16 pad)
static constexpr int TILE_B = 128 * ROWB;   // 10240
static constexpr int STAGE  = 4 * TILE_B;   // Ahi, Alo, Bhi, Blo = 40960
static constexpr uint32_t SMEM_BYTES = 2 * STAGE;  // 81920

template <int EPI, bool HAS_BIAS>
__global__ __launch_bounds__(256)
void gemm_mma(const __nv_bfloat16* __restrict__ Ahi, const __nv_bfloat16* __restrict__ Alo,
              const __nv_bfloat16* __restrict__ Bhi, const __nv_bfloat16* __restrict__ Blo,
              const float* __restrict__ bias,
              float* __restrict__ outF, __nv_bfloat16* __restrict__ outHi,
              __nv_bfloat16* __restrict__ outLo,
              int M, int N, int K, float alpha, size_t sA, size_t sB, size_t sC)
{
    extern __shared__ char smem[];
    const int tid = threadIdx.x;
    const int wid = tid >> 5;
    const int lane = tid & 31;

    Ahi += (size_t)blockIdx.z * sA; Alo += (size_t)blockIdx.z * sA;
    Bhi += (size_t)blockIdx.z * sB; Blo += (size_t)blockIdx.z * sB;
    float* outFb = outF; __nv_bfloat16 *outHib = outHi, *outLob = outLo;
    if (EPI == 0) outFb += (size_t)blockIdx.z * sC;
    else { outHib += (size_t)blockIdx.z * sC; outLob += (size_t)blockIdx.z * sC; }

    const int rowBase = blockIdx.y * 128;
    const int colBase = blockIdx.x * 128;
    const uint32_t sb = smem_u32(smem);

    // ---- async stage loader: 4 tiles x 128 rows x 64B; 2 cp16 per thread/tile
    auto ld_stage = [&](int t, int s) {
        const uint32_t base = sb + (uint32_t)s * STAGE;
        const int koff = t * KC;
        const int idx0 = tid * 2;
#pragma unroll
        for (int i = 0; i < 2; i++) {
            const int idx = idx0 + i;            // 0..511
            const int row = idx >> 2, ch = idx & 3;
            const uint32_t so = row * ROWB + ch * 16;
            const size_t ga = (size_t)(rowBase + row) * K + koff + ch * 8;
            const size_t gb = (size_t)(colBase + row) * K + koff + ch * 8;
            cp16(base + 0 * TILE_B + so, Ahi + ga);
            cp16(base + 1 * TILE_B + so, Alo + ga);
            cp16(base + 2 * TILE_B + so, Bhi + gb);
            cp16(base + 3 * TILE_B + so, Blo + gb);
        }
        CP_COMMIT();
    };

    // warp tiling: 4 (M) x 2 (N) warps; warp tile 32x64
    const int wm = (wid >> 1) * 32;
    const int wn = (wid & 1) * 64;

    // ldmatrix lane address components
    const int aRow = wm + (lane & 7) + ((lane >> 3) & 1) * 8;   // + mt*16
    const int aK8  = (lane >> 4) * 8;
    const int bRow = wn + ((lane >> 4) & 1) * 8 + (lane & 7);   // + p*16
    const int bK8  = ((lane >> 3) & 1) * 8;

    float acc[2][8][4];
#pragma unroll
    for (int mt = 0; mt < 2; mt++)
#pragma unroll
        for (int nt = 0; nt < 8; nt++)
#pragma unroll
            for (int q = 0; q < 4; q++) acc[mt][nt][q] = 0.0f;

    const int T = K / KC;
    ld_stage(0, 0);

    for (int t = 0; t < T; t++) {
        if (t + 1 < T) ld_stage(t + 1, (t + 1) & 1);
        if (t + 1 < T) { CP_WAIT(1); } else { CP_WAIT(0); }
        __syncthreads();

        const uint32_t base = sb + (uint32_t)(t & 1) * STAGE;
#pragma unroll
        for (int kk = 0; kk < 2; kk++) {
            const int k0 = kk * 16;
            uint32_t a_hi[2][4], a_lo[2][4], b_hi[4][4], b_lo[4][4];
#pragma unroll
            for (int mt = 0; mt < 2; mt++) {
                uint32_t ad = base + (uint32_t)((aRow + mt * 16) * ROWB + (k0 + aK8) * 2);
                ldm4(a_hi[mt], ad);
                ldm4(a_lo[mt], ad + TILE_B);
            }
#pragma unroll
            for (int p = 0; p < 4; p++) {
                uint32_t bd = base + 2 * TILE_B +
                              (uint32_t)((bRow + p * 16) * ROWB + (k0 + bK8) * 2);
                ldm4(b_hi[p], bd);
                ldm4(b_lo[p], bd + TILE_B);
            }
#pragma unroll
            for (int mt = 0; mt < 2; mt++)
#pragma unroll
                for (int nt = 0; nt < 8; nt++) {
                    const uint32_t* bh = &b_hi[nt >> 1][(nt & 1) * 2];
                    const uint32_t* bl = &b_lo[nt >> 1][(nt & 1) * 2];
                    mma16816(acc[mt][nt], a_hi[mt], bh);
                    mma16816(acc[mt][nt], a_hi[mt], bl);
                    mma16816(acc[mt][nt], a_lo[mt], bh);
                }
        }
        __syncthreads();
    }

    // ---- epilogue from registers
#pragma unroll
    for (int mt = 0; mt < 2; mt++) {
        const int r0 = rowBase + wm + mt * 16 + (lane >> 2);
#pragma unroll
        for (int nt = 0; nt < 8; nt++) {
            const int col = colBase + wn + nt * 8 + (lane & 3) * 2;
            float bx = 0.f, by = 0.f;
            if (HAS_BIAS) { bx = bias[col]; by = bias[col + 1]; }
#pragma unroll
            for (int half = 0; half < 2; half++) {
                const int r = r0 + half * 8;
                float f0 = acc[mt][nt][half * 2 + 0] * alpha + bx;
                float f1 = acc[mt][nt][half * 2 + 1] * alpha + by;
                if (EPI == 0) {
                    *reinterpret_cast<float2*>(&outFb[(size_t)r * N + col]) =
                        make_float2(f0, f1);
                } else {
                    __nv_bfloat16 h0 = __float2bfloat16_rn(f0);
                    __nv_bfloat16 h1 = __float2bfloat16_rn(f1);
                    __nv_bfloat16 l0 = __float2bfloat16_rn(f0 - __bfloat162float(h0));
                    __nv_bfloat16 l1 = __float2bfloat16_rn(f1 - __bfloat162float(h1));
                    __nv_bfloat162 hv; hv.x = h0; hv.y = h1;
                    __nv_bfloat162 lv; lv.x = l0; lv.y = l1;
                    *reinterpret_cast<__nv_bfloat162*>(&outHib[(size_t)r * N + col]) = hv;
                    *reinterpret_cast<__nv_bfloat162*>(&outLob[(size_t)r * N + col]) = lv;
                }
            }
        }
    }
}

// --------------------------- aux kernels -----------------------------------
__global__ void split_f32(const float* __restrict__ in, __nv_bfloat16* __restrict__ hi,
                          __nv_bfloat16* __restrict__ lo, size_t n4)
{
    size_t i = (size_t)blockIdx.x * blockDim.x + threadIdx.x;
    if (i >= n4) return;
    float4 v = reinterpret_cast<const float4*>(in)[i];
    float f[4] = {v.x, v.y, v.z, v.w};
    __nv_bfloat16 h[4], l[4];
#pragma unroll
    for (int j = 0; j < 4; j++) {
        h[j] = __float2bfloat16_rn(f[j]);
        l[j] = __float2bfloat16_rn(f[j] - __bfloat162float(h[j]));
    }
    __nv_bfloat162 h0; h0.x = h[0]; h0.y = h[1];
    __nv_bfloat162 h1; h1.x = h[2]; h1.y = h[3];
    __nv_bfloat162 l0; l0.x = l[0]; l0.y = l[1];
    __nv_bfloat162 l1; l1.x = l[2]; l1.y = l[3];
    reinterpret_cast<__nv_bfloat162*>(hi)[i * 2 + 0] = h0;
    reinterpret_cast<__nv_bfloat162*>(hi)[i * 2 + 1] = h1;
    reinterpret_cast<__nv_bfloat162*>(lo)[i * 2 + 0] = l0;
    reinterpret_cast<__nv_bfloat162*>(lo)[i * 2 + 1] = l1;
}

__global__ void transpose_split(const float* __restrict__ in, __nv_bfloat16* __restrict__ ohi,
                                __nv_bfloat16* __restrict__ olo, int R, int C)
{
    __shared__ float tile[32][33];
    in  += (size_t)blockIdx.z * R * C;
    ohi += (size_t)blockIdx.z * R * C;
    olo += (size_t)blockIdx.z * R * C;
    const int rb = blockIdx.y * 32, cb = blockIdx.x * 32;
    const int tx = threadIdx.x, ty = threadIdx.y;
#pragma unroll
    for (int i = ty; i < 32; i += 8)
        tile[i][tx] = in[(size_t)(rb + i) * C + cb + tx];
    __syncthreads();
#pragma unroll
    for (int i = ty; i < 32; i += 8) {
        float f = tile[tx][i];
        __nv_bfloat16 h = __float2bfloat16_rn(f);
        __nv_bfloat16 l = __float2bfloat16_rn(f - __bfloat162float(h));
        ohi[(size_t)(cb + i) * R + rb + tx] = h;
        olo[(size_t)(cb + i) * R + rb + tx] = l;
    }
}

__global__ void softmax_rows(float* __restrict__ Sm)
{
    const int row = blockIdx.x;
    const int tid = threadIdx.x;
    const int lane = tid & 31, warp = tid >> 5;
    float4* p = reinterpret_cast<float4*>(Sm + (size_t)row * S_);
    float4 v0 = p[tid], v1 = p[tid + 256];
    __shared__ float rM[8], rS[8];
    float m = fmaxf(fmaxf(fmaxf(v0.x, v0.y), fmaxf(v0.z, v0.w)),
                    fmaxf(fmaxf(v1.x, v1.y), fmaxf(v1.z, v1.w)));
#pragma unroll
    for (int o = 16; o > 0; o >>= 1) m = fmaxf(m, __shfl_xor_sync(~0u, m, o));
    if (lane == 0) rM[warp] = m;
    __syncthreads();
    float mA = rM[0];
#pragma unroll
    for (int w = 1; w < 8; w++) mA = fmaxf(mA, rM[w]);
    v0.x = __expf(v0.x - mA); v0.y = __expf(v0.y - mA);
    v0.z = __expf(v0.z - mA); v0.w = __expf(v0.w - mA);
    v1.x = __expf(v1.x - mA); v1.y = __expf(v1.y - mA);
    v1.z = __expf(v1.z - mA); v1.w = __expf(v1.w - mA);
    float s = (v0.x + v0.y) + (v0.z + v0.w) + (v1.x + v1.y) + (v1.z + v1.w);
#pragma unroll
    for (int o = 16; o > 0; o >>= 1) s += __shfl_xor_sync(~0u, s, o);
    if (lane == 0) rS[warp] = s;
    __syncthreads();
    float sA = 0.f;
#pragma unroll
    for (int w = 0; w < 8; w++) sA += rS[w];
    const float inv = 1.0f / sA;
    v0.x *= inv; v0.y *= inv; v0.z *= inv; v0.w *= inv;
    v1.x *= inv; v1.y *= inv; v1.z *= inv; v1.w *= inv;
    p[tid] = v0; p[tid + 256] = v1;
}

// ------------------------------- launch ------------------------------------
extern "C" void kernel_launch(void* const* d_in, const int* in_sizes, int n_in,
                              void* d_out, int out_size)
{
    const float* X  = (const float*)d_in[0];
    const float* Wq = (const float*)d_in[1];
    const float* bq = (const float*)d_in[2];
    const float* Wk = (const float*)d_in[3];
    const float* bk = (const float*)d_in[4];
    const float* Wv = (const float*)d_in[5];
    const float* bv = (const float*)d_in[6];
    const float* Wh = (const float*)d_in[7];
    const float* bh = (const float*)d_in[8];
    float* out = (float*)d_out;

    cudaFuncSetAttribute(gemm_mma<0, true>,  cudaFuncAttributeMaxDynamicSharedMemorySize, SMEM_BYTES);
    cudaFuncSetAttribute(gemm_mma<0, false>, cudaFuncAttributeMaxDynamicSharedMemorySize, SMEM_BYTES);
    cudaFuncSetAttribute(gemm_mma<1, true>,  cudaFuncAttributeMaxDynamicSharedMemorySize, SMEM_BYTES);
    cudaFuncSetAttribute(gemm_mma<1, false>, cudaFuncAttributeMaxDynamicSharedMemorySize, SMEM_BYTES);

    __nv_bfloat16 *Xhi, *Xlo, *Qhi, *Qlo, *Khi, *Klo, *VThi, *VTlo;
    __nv_bfloat16 *Phi, *Plo, *Chi, *Clo;
    __nv_bfloat16 *WqThi, *WqTlo, *WkThi, *WkTlo, *WvThi, *WvTlo, *WhThi, *WhTlo;
    float *Vf, *Sf;
    cudaGetSymbolAddress((void**)&Xhi, g_Xhi);   cudaGetSymbolAddress((void**)&Xlo, g_Xlo);
    cudaGetSymbolAddress((void**)&Qhi, g_Qhi);   cudaGetSymbolAddress((void**)&Qlo, g_Qlo);
    cudaGetSymbolAddress((void**)&Khi, g_Khi);   cudaGetSymbolAddress((void**)&Klo, g_Klo);
    cudaGetSymbolAddress((void**)&Vf,  g_Vf);
    cudaGetSymbolAddress((void**)&VThi, g_VThi); cudaGetSymbolAddress((void**)&VTlo, g_VTlo);
    cudaGetSymbolAddress((void**)&Sf,  g_Sf);
    cudaGetSymbolAddress((void**)&Phi, g_Phi);   cudaGetSymbolAddress((void**)&Plo, g_Plo);
    cudaGetSymbolAddress((void**)&Chi, g_Chi);   cudaGetSymbolAddress((void**)&Clo, g_Clo);
    cudaGetSymbolAddress((void**)&WqThi, g_WqThi); cudaGetSymbolAddress((void**)&WqTlo, g_WqTlo);
    cudaGetSymbolAddress((void**)&WkThi, g_WkThi); cudaGetSymbolAddress((void**)&WkTlo, g_WkTlo);
    cudaGetSymbolAddress((void**)&WvThi, g_WvThi); cudaGetSymbolAddress((void**)&WvTlo, g_WvTlo);
    cudaGetSymbolAddress((void**)&WhThi, g_WhThi); cudaGetSymbolAddress((void**)&WhTlo, g_WhTlo);

    // 1) split X; transpose+split weights
    {
        size_t n4 = (size_t)MTOT * H_ / 4;
        split_f32<<<(unsigned)((n4 + 255) / 256), 256>>>(X, Xhi, Xlo, n4);
        dim3 tb(32, 8), tg(H_ / 32, H_ / 32, 1);
        transpose_split<<<tg, tb>>>(Wq, WqThi, WqTlo, H_, H_);
        transpose_split<<<tg, tb>>>(Wk, WkThi, WkTlo, H_, H_);
        transpose_split<<<tg, tb>>>(Wv, WvThi, WvTlo, H_, H_);
        transpose_split<<<tg, tb>>>(Wh, WhThi, WhTlo, H_, H_);
    }

    // 2) projections
    {
        dim3 grid(H_ / 128, MTOT / 128, 1);
        gemm_mma<1, true><<<grid, 256, SMEM_BYTES>>>(Xhi, Xlo, WqThi, WqTlo, bq,
            nullptr, Qhi, Qlo, MTOT, H_, H_, 1.0f, 0, 0, 0);
        gemm_mma<1, true><<<grid, 256, SMEM_BYTES>>>(Xhi, Xlo, WkThi, WkTlo, bk,
            nullptr, Khi, Klo, MTOT, H_, H_, 1.0f, 0, 0, 0);
        gemm_mma<0, true><<<grid, 256, SMEM_BYTES>>>(Xhi, Xlo, WvThi, WvTlo, bv,
            Vf, nullptr, nullptr, MTOT, H_, H_, 1.0f, 0, 0, 0);
    }

    // 3) V^T split (per batch: [2048,1024] -> [1024,2048])
    {
        dim3 tb(32, 8), tg(H_ / 32, S_ / 32, B_);
        transpose_split<<<tg, tb>>>(Vf, VThi, VTlo, S_, H_);
    }

    // 4) scores = Q @ K^T / 32
    {
        dim3 grid(S_ / 128, S_ / 128, B_);
        gemm_mma<0, false><<<grid, 256, SMEM_BYTES>>>(Qhi, Qlo, Khi, Klo, nullptr,
            Sf, nullptr, nullptr, S_, S_, H_, 0.03125f,
            (size_t)S_ * H_, (size_t)S_ * H_, (size_t)S_ * S_);
    }

    // 5) softmax + split P
    softmax_rows<<<B_ * S_, 256>>>(Sf);
    {
        size_t n4 = (size_t)B_ * S_ * S_ / 4;
        split_f32<<<(unsigned)((n4 + 255) / 256), 256>>>(Sf, Phi, Plo, n4);
    }

    // 6) context = P @ V  (B operand = V^T [1024,2048])
    {
        dim3 grid(H_ / 128, S_ / 128, B_);
        gemm_mma<1, false><<<grid, 256, SMEM_BYTES>>>(Phi, Plo, VThi, VTlo, nullptr,
            nullptr, Chi, Clo, S_, H_, S_, 1.0f,
            (size_t)S_ * S_, (size_t)S_ * H_, (size_t)S_ * H_);
    }

    // 7) out = C @ Wh + bh
    {
        dim3 grid(H_ / 128, MTOT / 128, 1);
        gemm_mma<0, true><<<grid, 256, SMEM_BYTES>>>(Chi, Clo, WhThi, WhTlo, bh,
            out, nullptr, nullptr, MTOT, H_, H_, 1.0f, 0, 0, 0);
    }
}